// round 13
// baseline (speedup 1.0000x reference)
#include <cuda_runtime.h>
#include <cuda_bf16.h>
#include <math.h>
#include <stdint.h>

// Problem constants (fixed by the dataset problem)
#define NN    10000
#define EE    30000
#define INDIM 1024
#define H1N   4
#define C1N   512
#define D1N   2048   // H1*C1
#define H2N   8
#define C2N   460
#define D2N   3680   // H2*C2
#define E2N   40000  // EE + NN (self loops appended)

// ---------------- scratch (static device globals; no runtime allocation) ----
__device__ float g_Q [(size_t)NN * D1N];
__device__ float g_K [(size_t)NN * D1N];
__device__ float g_V [(size_t)NN * D1N];
__device__ float g_H [(size_t)NN * D1N];   // skip -> agg -> elu(h)
__device__ float g_GL[(size_t)NN * D2N];
__device__ float g_GR[(size_t)NN * D2N];

__device__ int   g_src[EE];
__device__ int   g_dst[EE];
__device__ int   g_is64;               // edge_index dtype flag (1 = int64)

__device__ float g_alpha1[EE * H1N];   // raw scores, then exp()
__device__ int   g_max1  [NN * H1N];
__device__ float g_sum1  [NN * H1N];

__device__ float g_a2  [E2N * H2N];    // raw scores, then exp()
__device__ int   g_max2[NN * H2N];
__device__ float g_sum2[NN * H2N];

// monotone int encoding of float for atomicMax
__device__ __forceinline__ int fenc(float f) {
    int i = __float_as_int(f);
    return (i >= 0) ? i : (i ^ 0x7fffffff);
}
__device__ __forceinline__ float fdec(int i) {
    return __int_as_float((i >= 0) ? i : (i ^ 0x7fffffff));
}

__device__ __forceinline__ float warp_sum(float v) {
    #pragma unroll
    for (int o = 16; o > 0; o >>= 1) v += __shfl_down_sync(0xffffffffu, v, o);
    return v;
}

// float -> tf32 bits (round to nearest)
__device__ __forceinline__ uint32_t f2tf32(float f) {
    uint32_t r;
    asm("cvt.rna.tf32.f32 %0, %1;" : "=r"(r) : "f"(f));
    return r;
}

// ---------------- edge-index dtype detection + unpack -----------------------
__global__ void detect_idx_kernel(const int* __restrict__ w) {
    int all0 = 1;
    #pragma unroll
    for (int i = 1; i < 128; i += 2)
        if (w[i] != 0) { all0 = 0; break; }
    g_is64 = all0;
}

__global__ void unpack_idx_kernel(const void* __restrict__ ei) {
    int e = blockIdx.x * blockDim.x + threadIdx.x;
    if (e >= EE) return;
    if (g_is64) {
        const long long* p = (const long long*)ei;
        g_src[e] = (int)p[2 * e];
        g_dst[e] = (int)p[2 * e + 1];
    } else {
        const int* p = (const int*)ei;
        g_src[e] = p[2 * e];
        g_dst[e] = p[2 * e + 1];
    }
}

// ---------------- init ------------------------------------------------------
__global__ void init_stats_kernel() {
    int i = blockIdx.x * blockDim.x + threadIdx.x;
    if (i < NN * H1N) { g_max1[i] = (int)0x80000000; g_sum1[i] = 0.f; }
    if (i < NN * H2N) { g_max2[i] = (int)0x80000000; g_sum2[i] = 0.f; }
}

__global__ void out_init_kernel(const float* __restrict__ b_out, float* __restrict__ out) {
    int i = blockIdx.x * blockDim.x + threadIdx.x;
    if (i < NN * C2N) out[i] = __ldg(&b_out[i % C2N]);
}

// ---------------- TF32 tensor-core GEMM: C = A(MxK) @ B(KxN) + bias(N) ------
// 128x128 CTA tile, BK=16, 128 threads = 4 warps (2M x 2N), warp tile 64x64.
// Fat warp tiles cut fragment re-reads: A dup 4->2, B dup 2->2 (smem-bound fix).
// mma.sync.m16n8k8.tf32; stride-136 smem => conflict-free fragment LDS and
// conflict-free A stores. Double-buffered smem + register prefetch.
__global__ __launch_bounds__(128) void sgemm_tf32(
    int M, int N, int K,
    const float* __restrict__ A,
    const float* __restrict__ B,
    const float* __restrict__ bias,
    float* __restrict__ C)
{
    __shared__ __align__(16) uint32_t As[2][16][136];   // [buf][k][row]
    __shared__ __align__(16) uint32_t Bs[2][16][136];   // [buf][k][col]

    const int tid  = threadIdx.x;
    const int wid  = tid >> 5;
    const int lane = tid & 31;
    const int gid  = lane >> 2;          // 0..7
    const int tig  = lane & 3;           // 0..3
    const int warpM = wid >> 1;          // 0..1
    const int warpN = wid & 1;           // 0..1

    const int blockRow = blockIdx.y * 128;
    const int blockCol = blockIdx.x * 128;

    // global-load roles:
    //   A: thread tid owns row tid, k0..k0+15 (4 float4 along K)
    //   B: thread owns row k0+(tid>>3), cols (tid&7)*16 .. +15 (4 float4)
    const int aRow = tid;                // 0..127
    const int bRow = tid >> 3;           // 0..15
    const int bCol = (tid & 7) * 16;     // 0..112

    const int gr = blockRow + aRow;
    const int gc = blockCol + bCol;
    const bool aOK = (gr < M);

    const float* Abase = A + (size_t)gr * K;          // deref only if aOK
    const float* Bbase = B + (size_t)bRow * N + gc;

    float acc[4][8][4];
    #pragma unroll
    for (int mt = 0; mt < 4; mt++)
        #pragma unroll
        for (int nt = 0; nt < 8; nt++)
            #pragma unroll
            for (int i = 0; i < 4; i++) acc[mt][nt][i] = 0.f;

    float af[16], bf[16];

    // ---- slice loader into registers ----
    auto load_slice = [&](int k0) {
        #pragma unroll
        for (int j = 0; j < 4; j++) {
            float4 v = make_float4(0.f, 0.f, 0.f, 0.f);
            if (aOK) v = *reinterpret_cast<const float4*>(Abase + k0 + j * 4);
            af[j * 4 + 0] = v.x; af[j * 4 + 1] = v.y;
            af[j * 4 + 2] = v.z; af[j * 4 + 3] = v.w;
        }
        #pragma unroll
        for (int j = 0; j < 4; j++) {
            const float* bp = Bbase + (size_t)k0 * N + j * 4;
            int c = gc + j * 4;
            float4 v;
            if (c + 3 < N) {
                v = *reinterpret_cast<const float4*>(bp);
            } else {
                v.x = (c + 0 < N) ? bp[0] : 0.f;
                v.y = (c + 1 < N) ? bp[1] : 0.f;
                v.z = (c + 2 < N) ? bp[2] : 0.f;
                v.w = (c + 3 < N) ? bp[3] : 0.f;
            }
            bf[j * 4 + 0] = v.x; bf[j * 4 + 1] = v.y;
            bf[j * 4 + 2] = v.z; bf[j * 4 + 3] = v.w;
        }
    };

    // ---- slice storer (tf32 convert; A transposed scalar, B STS.128) ----
    auto store_slice = [&](int nb) {
        #pragma unroll
        for (int k = 0; k < 16; k++)
            As[nb][k][aRow] = f2tf32(af[k]);          // 32 consecutive rows: conflict-free
        #pragma unroll
        for (int j = 0; j < 4; j++) {
            uint4 p = make_uint4(f2tf32(bf[j*4+0]), f2tf32(bf[j*4+1]),
                                 f2tf32(bf[j*4+2]), f2tf32(bf[j*4+3]));
            *reinterpret_cast<uint4*>(&Bs[nb][bRow][bCol + j * 4]) = p;
        }
    };

    load_slice(0);
    store_slice(0);
    __syncthreads();

    const int rA = warpM * 64 + gid;     // + mt*16 (+8)
    const int cB = warpN * 64 + gid;     // + nt*8

    int buf = 0;
    for (int k0 = 0; k0 < K; k0 += 16) {
        const int kn = k0 + 16;

        // ---- prefetch next 16-slice into registers (overlaps 64 mma) ----
        if (kn < K) load_slice(kn);

        // ---- two k8 halves ----
        #pragma unroll
        for (int kk = 0; kk < 2; kk++) {
            const int o = kk * 8;
            uint32_t afr[4][4];
            uint32_t bfr[8][2];
            #pragma unroll
            for (int mt = 0; mt < 4; mt++) {
                int r = rA + mt * 16;
                afr[mt][0] = As[buf][o + tig    ][r];
                afr[mt][1] = As[buf][o + tig    ][r + 8];
                afr[mt][2] = As[buf][o + tig + 4][r];
                afr[mt][3] = As[buf][o + tig + 4][r + 8];
            }
            #pragma unroll
            for (int nt = 0; nt < 8; nt++) {
                int c = cB + nt * 8;
                bfr[nt][0] = Bs[buf][o + tig    ][c];
                bfr[nt][1] = Bs[buf][o + tig + 4][c];
            }
            #pragma unroll
            for (int mt = 0; mt < 4; mt++)
                #pragma unroll
                for (int nt = 0; nt < 8; nt++) {
                    asm volatile(
                        "mma.sync.aligned.m16n8k8.row.col.f32.tf32.tf32.f32 "
                        "{%0,%1,%2,%3}, {%4,%5,%6,%7}, {%8,%9}, {%0,%1,%2,%3};\n"
                        : "+f"(acc[mt][nt][0]), "+f"(acc[mt][nt][1]),
                          "+f"(acc[mt][nt][2]), "+f"(acc[mt][nt][3])
                        : "r"(afr[mt][0]), "r"(afr[mt][1]),
                          "r"(afr[mt][2]), "r"(afr[mt][3]),
                          "r"(bfr[nt][0]), "r"(bfr[nt][1]));
                }
        }

        // ---- store prefetched slice into the other buffer ----
        if (kn < K) {
            int nb = buf ^ 1;
            store_slice(nb);
            __syncthreads();          // one barrier per 16-deep slice
            buf = nb;
        }
    }

    // ---- epilogue: bias + guarded stores ----
    #pragma unroll
    for (int mt = 0; mt < 4; mt++) {
        int r0 = blockRow + warpM * 64 + mt * 16 + gid;
        #pragma unroll
        for (int nt = 0; nt < 8; nt++) {
            int c0 = blockCol + warpN * 64 + nt * 8 + tig * 2;
            float bb0 = (c0     < N) ? __ldg(&bias[c0])     : 0.f;
            float bb1 = (c0 + 1 < N) ? __ldg(&bias[c0 + 1]) : 0.f;
            if (r0 < M) {
                if (c0     < N) C[(size_t)r0 * N + c0]     = acc[mt][nt][0] + bb0;
                if (c0 + 1 < N) C[(size_t)r0 * N + c0 + 1] = acc[mt][nt][1] + bb1;
            }
            if (r0 + 8 < M) {
                if (c0     < N) C[(size_t)(r0 + 8) * N + c0]     = acc[mt][nt][2] + bb0;
                if (c0 + 1 < N) C[(size_t)(r0 + 8) * N + c0 + 1] = acc[mt][nt][3] + bb1;
            }
        }
    }
}

// ---------------- layer 1 edge ops ------------------------------------------
__global__ void edge_alpha1_kernel() {
    int e = blockIdx.x;
    int h = threadIdx.x >> 5;
    int lane = threadIdx.x & 31;
    int s = g_src[e];
    int d = g_dst[e];
    const float4* qp = (const float4*)(g_Q + (size_t)d * D1N + h * C1N);
    const float4* kp = (const float4*)(g_K + (size_t)s * D1N + h * C1N);
    float acc = 0.f;
    #pragma unroll
    for (int c = lane; c < C1N / 4; c += 32) {
        float4 q4 = qp[c], k4 = kp[c];
        acc += q4.x * k4.x + q4.y * k4.y + q4.z * k4.z + q4.w * k4.w;
    }
    acc = warp_sum(acc);
    if (lane == 0) {
        float val = acc * 0.044194173824159216f;  // 1/sqrt(512)
        g_alpha1[e * H1N + h] = val;
        atomicMax(&g_max1[d * H1N + h], fenc(val));
    }
}

__global__ void exp1_kernel() {
    int idx = blockIdx.x * blockDim.x + threadIdx.x;
    if (idx >= EE * H1N) return;
    int e = idx / H1N;
    int h = idx - e * H1N;
    int d = g_dst[e];
    float m  = fdec(g_max1[d * H1N + h]);
    float ex = expf(g_alpha1[idx] - m);
    g_alpha1[idx] = ex;
    atomicAdd(&g_sum1[d * H1N + h], ex);
}

__global__ void agg1_kernel() {
    int e = blockIdx.x;
    int s = g_src[e];
    int d = g_dst[e];
    __shared__ float w[H1N];
    if (threadIdx.x < H1N)
        w[threadIdx.x] = g_alpha1[e * H1N + threadIdx.x] /
                         (g_sum1[d * H1N + threadIdx.x] + 1e-16f);
    __syncthreads();
    const float4* vp = (const float4*)(g_V + (size_t)s * D1N);
    float* ap = g_H + (size_t)d * D1N;
    for (int j = threadIdx.x; j < D1N / 4; j += 256) {
        float4 v4 = vp[j];
        float wt = w[j >> 7];
        int base = j * 4;
        atomicAdd(&ap[base + 0], v4.x * wt);
        atomicAdd(&ap[base + 1], v4.y * wt);
        atomicAdd(&ap[base + 2], v4.z * wt);
        atomicAdd(&ap[base + 3], v4.w * wt);
    }
}

__global__ void elu_kernel() {
    int i = blockIdx.x * blockDim.x + threadIdx.x;
    if (i < (NN * D1N) / 4) {
        float4* p = (float4*)g_H;
        float4 v = p[i];
        v.x = (v.x > 0.f) ? v.x : expm1f(v.x);
        v.y = (v.y > 0.f) ? v.y : expm1f(v.y);
        v.z = (v.z > 0.f) ? v.z : expm1f(v.z);
        v.w = (v.w > 0.f) ? v.w : expm1f(v.w);
        p[i] = v;
    }
}

// ---------------- layer 2 edge ops ------------------------------------------
__global__ void edge_a2_kernel(const float* __restrict__ att) {
    int e = blockIdx.x;
    int h = threadIdx.x >> 5;
    int lane = threadIdx.x & 31;
    int s, d;
    if (e < EE) { s = g_src[e]; d = g_dst[e]; }
    else        { s = e - EE; d = e - EE; }
    const float* glp = g_GL + (size_t)s * D2N + h * C2N;
    const float* grp = g_GR + (size_t)d * D2N + h * C2N;
    const float* ap  = att + h * C2N;
    float acc = 0.f;
    for (int c = lane; c < C2N; c += 32) {
        float v = glp[c] + grp[c];
        v = (v > 0.f) ? v : 0.2f * v;           // leaky_relu(0.2)
        acc += v * __ldg(&ap[c]);
    }
    acc = warp_sum(acc);
    if (lane == 0) {
        g_a2[e * H2N + h] = acc;
        atomicMax(&g_max2[d * H2N + h], fenc(acc));
    }
}

__global__ void exp2_kernel() {
    int idx = blockIdx.x * blockDim.x + threadIdx.x;
    if (idx >= E2N * H2N) return;
    int e = idx / H2N;
    int h = idx - e * H2N;
    int d = (e < EE) ? g_dst[e] : (e - EE);
    float m  = fdec(g_max2[d * H2N + h]);
    float ex = expf(g_a2[idx] - m);
    g_a2[idx] = ex;
    atomicAdd(&g_sum2[d * H2N + h], ex);
}

__global__ void out_acc_kernel(float* __restrict__ out) {
    int e = blockIdx.x;
    int s, d;
    if (e < EE) { s = g_src[e]; d = g_dst[e]; }
    else        { s = e - EE; d = e - EE; }
    __shared__ float w[H2N];
    if (threadIdx.x < H2N)
        w[threadIdx.x] = g_a2[e * H2N + threadIdx.x] /
                         (g_sum2[d * H2N + threadIdx.x] + 1e-16f) * 0.125f;
    __syncthreads();
    const float* glp = g_GL + (size_t)s * D2N;
    float* op = out + (size_t)d * C2N;
    for (int c = threadIdx.x; c < C2N; c += 256) {
        float acc = 0.f;
        #pragma unroll
        for (int h = 0; h < H2N; h++)
            acc += __ldg(&glp[h * C2N + c]) * w[h];
        atomicAdd(&op[c], acc);
    }
}

// ---------------- host ------------------------------------------------------
extern "C" void kernel_launch(void* const* d_in, const int* in_sizes, int n_in,
                              void* d_out, int out_size) {
    const float* x     = (const float*)d_in[0];
    const void*  ei    = d_in[1];               // dtype detected on device
    const float* Wq    = (const float*)d_in[2];
    const float* bq    = (const float*)d_in[3];
    const float* Wk    = (const float*)d_in[4];
    const float* bk    = (const float*)d_in[5];
    const float* Wv    = (const float*)d_in[6];
    const float* bv    = (const float*)d_in[7];
    const float* Wsk   = (const float*)d_in[8];
    const float* bsk   = (const float*)d_in[9];
    const float* Wl    = (const float*)d_in[10];
    const float* bl    = (const float*)d_in[11];
    const float* Wr    = (const float*)d_in[12];
    const float* br    = (const float*)d_in[13];
    const float* att   = (const float*)d_in[14];
    const float* b_out = (const float*)d_in[15];
    float*       out   = (float*)d_out;

    static float *pQ = nullptr, *pK = nullptr, *pV = nullptr,
                 *pH = nullptr, *pGL = nullptr, *pGR = nullptr;
    if (!pQ) {
        void* p;
        cudaGetSymbolAddress(&p, g_Q);  pQ  = (float*)p;
        cudaGetSymbolAddress(&p, g_K);  pK  = (float*)p;
        cudaGetSymbolAddress(&p, g_V);  pV  = (float*)p;
        cudaGetSymbolAddress(&p, g_H);  pH  = (float*)p;
        cudaGetSymbolAddress(&p, g_GL); pGL = (float*)p;
        cudaGetSymbolAddress(&p, g_GR); pGR = (float*)p;
    }

    // layer-1 projections FIRST (keeps sgemm in ncu's fixed sampling window)
    dim3 g1(D1N / 128, (NN + 127) / 128);
    sgemm_tf32<<<g1, 128>>>(NN, D1N, INDIM, x, Wq,  bq,  pQ);
    sgemm_tf32<<<g1, 128>>>(NN, D1N, INDIM, x, Wk,  bk,  pK);
    sgemm_tf32<<<g1, 128>>>(NN, D1N, INDIM, x, Wv,  bv,  pV);
    sgemm_tf32<<<g1, 128>>>(NN, D1N, INDIM, x, Wsk, bsk, pH);

    // edge-index dtype detection + unpack; stats + output init
    detect_idx_kernel<<<1, 1>>>((const int*)ei);
    unpack_idx_kernel<<<(EE + 255) / 256, 256>>>(ei);
    init_stats_kernel<<<(NN * H2N + 255) / 256, 256>>>();
    out_init_kernel<<<(NN * C2N + 255) / 256, 256>>>(b_out, out);

    // layer-1 attention + aggregation
    edge_alpha1_kernel<<<EE, H1N * 32>>>();
    exp1_kernel<<<(EE * H1N + 255) / 256, 256>>>();
    agg1_kernel<<<EE, 256>>>();
    elu_kernel<<<((NN * D1N) / 4 + 255) / 256, 256>>>();

    // layer-2 projections: M=10000, K=2048, N=3680
    dim3 g2((D2N + 127) / 128, (NN + 127) / 128);
    sgemm_tf32<<<g2, 128>>>(NN, D2N, D1N, pH, Wl, bl, pGL);
    sgemm_tf32<<<g2, 128>>>(NN, D2N, D1N, pH, Wr, br, pGR);

    // layer-2 attention + output
    edge_a2_kernel<<<E2N, H2N * 32>>>(att);
    exp2_kernel<<<(E2N * H2N + 255) / 256, 256>>>();
    out_acc_kernel<<<E2N, 256>>>(out);
}

// round 14
// speedup vs baseline: 1.7030x; 1.7030x over previous
#include <cuda_runtime.h>
#include <cuda_bf16.h>
#include <math.h>
#include <stdint.h>

// Problem constants (fixed by the dataset problem)
#define NN    10000
#define EE    30000
#define INDIM 1024
#define H1N   4
#define C1N   512
#define D1N   2048   // H1*C1
#define H2N   8
#define C2N   460
#define D2N   3680   // H2*C2
#define E2N   40000  // EE + NN (self loops appended)

// ---------------- scratch (static device globals; no runtime allocation) ----
__device__ float g_Q [(size_t)NN * D1N];
__device__ float g_K [(size_t)NN * D1N];
__device__ float g_V [(size_t)NN * D1N];
__device__ float g_H [(size_t)NN * D1N];   // skip -> agg -> elu(h)
__device__ float g_GL[(size_t)NN * D2N];
__device__ float g_GR[(size_t)NN * D2N];

// tf32-preconverted operands (rna), so the GEMM can cp.async raw bits
__device__ float g_Xc [(size_t)NN * INDIM];
__device__ float g_Hc [(size_t)NN * D1N];
__device__ float g_Wqc[(size_t)INDIM * D1N];
__device__ float g_Wkc[(size_t)INDIM * D1N];
__device__ float g_Wvc[(size_t)INDIM * D1N];
__device__ float g_Wsc[(size_t)INDIM * D1N];
__device__ float g_Wlc[(size_t)D1N * D2N];
__device__ float g_Wrc[(size_t)D1N * D2N];

__device__ int   g_src[EE];
__device__ int   g_dst[EE];
__device__ int   g_is64;               // edge_index dtype flag (1 = int64)

__device__ float g_alpha1[EE * H1N];   // raw scores, then exp()
__device__ int   g_max1  [NN * H1N];
__device__ float g_sum1  [NN * H1N];

__device__ float g_a2  [E2N * H2N];    // raw scores, then exp()
__device__ int   g_max2[NN * H2N];
__device__ float g_sum2[NN * H2N];

// monotone int encoding of float for atomicMax
__device__ __forceinline__ int fenc(float f) {
    int i = __float_as_int(f);
    return (i >= 0) ? i : (i ^ 0x7fffffff);
}
__device__ __forceinline__ float fdec(int i) {
    return __int_as_float((i >= 0) ? i : (i ^ 0x7fffffff));
}

__device__ __forceinline__ float warp_sum(float v) {
    #pragma unroll
    for (int o = 16; o > 0; o >>= 1) v += __shfl_down_sync(0xffffffffu, v, o);
    return v;
}

// float -> tf32 bits (round to nearest)
__device__ __forceinline__ uint32_t f2tf32(float f) {
    uint32_t r;
    asm("cvt.rna.tf32.f32 %0, %1;" : "=r"(r) : "f"(f));
    return r;
}

// 16B cp.async with zero-fill predicate (src-size 0 => zfill)
__device__ __forceinline__ void cp16(uint32_t saddr, const void* gptr, bool ok) {
    int sz = ok ? 16 : 0;
    asm volatile("cp.async.cg.shared.global [%0], [%1], 16, %2;\n"
                 :: "r"(saddr), "l"(gptr), "r"(sz));
}
__device__ __forceinline__ uint32_t smem_u32(const void* p) {
    return (uint32_t)__cvta_generic_to_shared(p);
}

// ---------------- tf32 pre-convert (rna) ------------------------------------
__global__ void cvt_tf32_kernel(const float* __restrict__ in,
                                float* __restrict__ out, int n4) {
    int i = blockIdx.x * blockDim.x + threadIdx.x;
    if (i < n4) {
        float4 v = reinterpret_cast<const float4*>(in)[i];
        uint4 o;
        o.x = f2tf32(v.x); o.y = f2tf32(v.y);
        o.z = f2tf32(v.z); o.w = f2tf32(v.w);
        reinterpret_cast<uint4*>(out)[i] = o;
    }
}

// ---------------- edge-index dtype detection + unpack -----------------------
__global__ void detect_idx_kernel(const int* __restrict__ w) {
    int all0 = 1;
    #pragma unroll
    for (int i = 1; i < 128; i += 2)
        if (w[i] != 0) { all0 = 0; break; }
    g_is64 = all0;
}

__global__ void unpack_idx_kernel(const void* __restrict__ ei) {
    int e = blockIdx.x * blockDim.x + threadIdx.x;
    if (e >= EE) return;
    if (g_is64) {
        const long long* p = (const long long*)ei;
        g_src[e] = (int)p[2 * e];
        g_dst[e] = (int)p[2 * e + 1];
    } else {
        const int* p = (const int*)ei;
        g_src[e] = p[2 * e];
        g_dst[e] = p[2 * e + 1];
    }
}

// ---------------- init ------------------------------------------------------
__global__ void init_stats_kernel() {
    int i = blockIdx.x * blockDim.x + threadIdx.x;
    if (i < NN * H1N) { g_max1[i] = (int)0x80000000; g_sum1[i] = 0.f; }
    if (i < NN * H2N) { g_max2[i] = (int)0x80000000; g_sum2[i] = 0.f; }
}

__global__ void out_init_kernel(const float* __restrict__ b_out, float* __restrict__ out) {
    int i = blockIdx.x * blockDim.x + threadIdx.x;
    if (i < NN * C2N) out[i] = __ldg(&b_out[i % C2N]);
}

// ---------------- TF32 tensor-core GEMM (pre-converted operands) ------------
// 128x128 CTA tile, BK=16, 256 threads = 8 warps (2M x 4N), warp tile 64x32.
// Operands pre-converted to tf32 bits; cp.async 3-stage pipeline feeds smem.
// A row-major stride 20 (conflict-free frag LDS), B stride 136 (conflict-free).
#define ASTR 20
#define BSTR 136
#define AWORDS (128 * ASTR)          // 2560
#define BWORDS (16 * BSTR)           // 2176
#define SMEM_BYTES ((3 * AWORDS + 3 * BWORDS) * 4)   // 56832

__global__ __launch_bounds__(256, 2) void sgemm_tf32(
    int M, int N, int K,
    const float* __restrict__ A,     // tf32-bit fp32, MxK row-major
    const float* __restrict__ B,     // tf32-bit fp32, KxN row-major
    const float* __restrict__ bias,
    float* __restrict__ C)
{
    extern __shared__ uint32_t sm[];
    uint32_t* Asm = sm;                       // 3 stages of [128][ASTR]
    uint32_t* Bsm = sm + 3 * AWORDS;          // 3 stages of [16][BSTR]

    const int tid  = threadIdx.x;
    const int wid  = tid >> 5;
    const int lane = tid & 31;
    const int gid  = lane >> 2;          // 0..7
    const int tig  = lane & 3;           // 0..3
    const int warpM = wid >> 2;          // 0..1
    const int warpN = wid & 3;           // 0..3

    const int blockRow = blockIdx.y * 128;
    const int blockCol = blockIdx.x * 128;

    // copy roles: A 128x16 (two 16B chunks/thread), B 16x128 (two chunks)
    const int arow = tid >> 2;           // 0..63 (+64)
    const int akc  = (tid & 3) * 4;      // k offset 0,4,8,12
    const int brow = tid >> 5;           // 0..7 (+8)
    const int bcol = (tid & 31) * 4;     // 0..124

    const int gc = blockCol + bcol;
    const bool bOK = (gc < N);           // N % 4 == 0 => whole chunk in/out

    auto issue = [&](int k0, int stg) {
        uint32_t* as = Asm + stg * AWORDS;
        uint32_t* bs = Bsm + stg * BWORDS;
        #pragma unroll
        for (int j = 0; j < 2; j++) {
            int row = arow + j * 64;
            int gr  = blockRow + row;
            cp16(smem_u32(as + row * ASTR + akc),
                 A + (size_t)gr * K + k0 + akc, gr < M);
        }
        #pragma unroll
        for (int j = 0; j < 2; j++) {
            int row = brow + j * 8;
            cp16(smem_u32(bs + row * BSTR + bcol),
                 B + (size_t)(k0 + row) * N + gc, bOK);
        }
        asm volatile("cp.async.commit_group;\n" ::: "memory");
    };

    float acc[4][4][4];
    #pragma unroll
    for (int mt = 0; mt < 4; mt++)
        #pragma unroll
        for (int nt = 0; nt < 4; nt++)
            #pragma unroll
            for (int i = 0; i < 4; i++) acc[mt][nt][i] = 0.f;

    // prologue: 2 stages in flight (K >= 32 always here)
    issue(0, 0);
    issue(16, 1);
    asm volatile("cp.async.wait_group 1;\n" ::: "memory");
    __syncthreads();

    const int rA = warpM * 64 + gid;     // + mt*16 (+8)
    const int cB = warpN * 32 + gid;     // + nt*8

    int buf = 0;
    for (int k0 = 0; k0 < K; k0 += 16) {
        const int kpre = k0 + 32;
        const bool morePre = (kpre < K);
        if (morePre) issue(kpre, (buf + 2) % 3);

        const uint32_t* as = Asm + buf * AWORDS;
        const uint32_t* bs = Bsm + buf * BWORDS;

        #pragma unroll
        for (int kk = 0; kk < 2; kk++) {
            const int o = kk * 8;
            uint32_t afr[4][4];
            uint32_t bfr[4][2];
            #pragma unroll
            for (int mt = 0; mt < 4; mt++) {
                int r = rA + mt * 16;
                afr[mt][0] = as[(size_t)r * ASTR + o + tig];
                afr[mt][1] = as[(size_t)(r + 8) * ASTR + o + tig];
                afr[mt][2] = as[(size_t)r * ASTR + o + tig + 4];
                afr[mt][3] = as[(size_t)(r + 8) * ASTR + o + tig + 4];
            }
            #pragma unroll
            for (int nt = 0; nt < 4; nt++) {
                int c = cB + nt * 8;
                bfr[nt][0] = bs[(size_t)(o + tig) * BSTR + c];
                bfr[nt][1] = bs[(size_t)(o + tig + 4) * BSTR + c];
            }
            #pragma unroll
            for (int mt = 0; mt < 4; mt++)
                #pragma unroll
                for (int nt = 0; nt < 4; nt++) {
                    asm volatile(
                        "mma.sync.aligned.m16n8k8.row.col.f32.tf32.tf32.f32 "
                        "{%0,%1,%2,%3}, {%4,%5,%6,%7}, {%8,%9}, {%0,%1,%2,%3};\n"
                        : "+f"(acc[mt][nt][0]), "+f"(acc[mt][nt][1]),
                          "+f"(acc[mt][nt][2]), "+f"(acc[mt][nt][3])
                        : "r"(afr[mt][0]), "r"(afr[mt][1]),
                          "r"(afr[mt][2]), "r"(afr[mt][3]),
                          "r"(bfr[nt][0]), "r"(bfr[nt][1]));
                }
        }

        if (k0 + 16 < K) {
            if (morePre) {
                asm volatile("cp.async.wait_group 1;\n" ::: "memory");
            } else {
                asm volatile("cp.async.wait_group 0;\n" ::: "memory");
            }
            __syncthreads();
            buf = (buf + 1) % 3;
        }
    }

    // ---- epilogue: bias + guarded stores ----
    #pragma unroll
    for (int mt = 0; mt < 4; mt++) {
        int r0 = blockRow + warpM * 64 + mt * 16 + gid;
        #pragma unroll
        for (int nt = 0; nt < 4; nt++) {
            int c0 = blockCol + warpN * 32 + nt * 8 + tig * 2;
            float bb0 = (c0     < N) ? __ldg(&bias[c0])     : 0.f;
            float bb1 = (c0 + 1 < N) ? __ldg(&bias[c0 + 1]) : 0.f;
            if (r0 < M) {
                if (c0     < N) C[(size_t)r0 * N + c0]     = acc[mt][nt][0] + bb0;
                if (c0 + 1 < N) C[(size_t)r0 * N + c0 + 1] = acc[mt][nt][1] + bb1;
            }
            if (r0 + 8 < M) {
                if (c0     < N) C[(size_t)(r0 + 8) * N + c0]     = acc[mt][nt][2] + bb0;
                if (c0 + 1 < N) C[(size_t)(r0 + 8) * N + c0 + 1] = acc[mt][nt][3] + bb1;
            }
        }
    }
}

// ---------------- layer 1 edge ops ------------------------------------------
__global__ void edge_alpha1_kernel() {
    int e = blockIdx.x;
    int h = threadIdx.x >> 5;
    int lane = threadIdx.x & 31;
    int s = g_src[e];
    int d = g_dst[e];
    const float4* qp = (const float4*)(g_Q + (size_t)d * D1N + h * C1N);
    const float4* kp = (const float4*)(g_K + (size_t)s * D1N + h * C1N);
    float acc = 0.f;
    #pragma unroll
    for (int c = lane; c < C1N / 4; c += 32) {
        float4 q4 = qp[c], k4 = kp[c];
        acc += q4.x * k4.x + q4.y * k4.y + q4.z * k4.z + q4.w * k4.w;
    }
    acc = warp_sum(acc);
    if (lane == 0) {
        float val = acc * 0.044194173824159216f;  // 1/sqrt(512)
        g_alpha1[e * H1N + h] = val;
        atomicMax(&g_max1[d * H1N + h], fenc(val));
    }
}

__global__ void exp1_kernel() {
    int idx = blockIdx.x * blockDim.x + threadIdx.x;
    if (idx >= EE * H1N) return;
    int e = idx / H1N;
    int h = idx - e * H1N;
    int d = g_dst[e];
    float m  = fdec(g_max1[d * H1N + h]);
    float ex = expf(g_alpha1[idx] - m);
    g_alpha1[idx] = ex;
    atomicAdd(&g_sum1[d * H1N + h], ex);
}

__global__ void agg1_kernel() {
    int e = blockIdx.x;
    int s = g_src[e];
    int d = g_dst[e];
    __shared__ float w[H1N];
    if (threadIdx.x < H1N)
        w[threadIdx.x] = g_alpha1[e * H1N + threadIdx.x] /
                         (g_sum1[d * H1N + threadIdx.x] + 1e-16f);
    __syncthreads();
    const float4* vp = (const float4*)(g_V + (size_t)s * D1N);
    float* ap = g_H + (size_t)d * D1N;
    for (int j = threadIdx.x; j < D1N / 4; j += 256) {
        float4 v4 = vp[j];
        float wt = w[j >> 7];
        int base = j * 4;
        atomicAdd(&ap[base + 0], v4.x * wt);
        atomicAdd(&ap[base + 1], v4.y * wt);
        atomicAdd(&ap[base + 2], v4.z * wt);
        atomicAdd(&ap[base + 3], v4.w * wt);
    }
}

// elu in place on g_H, plus tf32 copy into g_Hc for the layer-2 GEMMs
__global__ void elu_cvt_kernel() {
    int i = blockIdx.x * blockDim.x + threadIdx.x;
    if (i < (NN * D1N) / 4) {
        float4* p = (float4*)g_H;
        float4 v = p[i];
        v.x = (v.x > 0.f) ? v.x : expm1f(v.x);
        v.y = (v.y > 0.f) ? v.y : expm1f(v.y);
        v.z = (v.z > 0.f) ? v.z : expm1f(v.z);
        v.w = (v.w > 0.f) ? v.w : expm1f(v.w);
        p[i] = v;
        uint4 o;
        o.x = f2tf32(v.x); o.y = f2tf32(v.y);
        o.z = f2tf32(v.z); o.w = f2tf32(v.w);
        reinterpret_cast<uint4*>(g_Hc)[i] = o;
    }
}

// ---------------- layer 2 edge ops ------------------------------------------
__global__ void edge_a2_kernel(const float* __restrict__ att) {
    int e = blockIdx.x;
    int h = threadIdx.x >> 5;
    int lane = threadIdx.x & 31;
    int s, d;
    if (e < EE) { s = g_src[e]; d = g_dst[e]; }
    else        { s = e - EE; d = e - EE; }
    const float* glp = g_GL + (size_t)s * D2N + h * C2N;
    const float* grp = g_GR + (size_t)d * D2N + h * C2N;
    const float* ap  = att + h * C2N;
    float acc = 0.f;
    for (int c = lane; c < C2N; c += 32) {
        float v = glp[c] + grp[c];
        v = (v > 0.f) ? v : 0.2f * v;           // leaky_relu(0.2)
        acc += v * __ldg(&ap[c]);
    }
    acc = warp_sum(acc);
    if (lane == 0) {
        g_a2[e * H2N + h] = acc;
        atomicMax(&g_max2[d * H2N + h], fenc(acc));
    }
}

__global__ void exp2_kernel() {
    int idx = blockIdx.x * blockDim.x + threadIdx.x;
    if (idx >= E2N * H2N) return;
    int e = idx / H2N;
    int h = idx - e * H2N;
    int d = (e < EE) ? g_dst[e] : (e - EE);
    float m  = fdec(g_max2[d * H2N + h]);
    float ex = expf(g_a2[idx] - m);
    g_a2[idx] = ex;
    atomicAdd(&g_sum2[d * H2N + h], ex);
}

__global__ void out_acc_kernel(float* __restrict__ out) {
    int e = blockIdx.x;
    int s, d;
    if (e < EE) { s = g_src[e]; d = g_dst[e]; }
    else        { s = e - EE; d = e - EE; }
    __shared__ float w[H2N];
    if (threadIdx.x < H2N)
        w[threadIdx.x] = g_a2[e * H2N + threadIdx.x] /
                         (g_sum2[d * H2N + threadIdx.x] + 1e-16f) * 0.125f;
    __syncthreads();
    const float* glp = g_GL + (size_t)s * D2N;
    float* op = out + (size_t)d * C2N;
    for (int c = threadIdx.x; c < C2N; c += 256) {
        float acc = 0.f;
        #pragma unroll
        for (int h = 0; h < H2N; h++)
            acc += __ldg(&glp[h * C2N + c]) * w[h];
        atomicAdd(&op[c], acc);
    }
}

// ---------------- host ------------------------------------------------------
extern "C" void kernel_launch(void* const* d_in, const int* in_sizes, int n_in,
                              void* d_out, int out_size) {
    const float* x     = (const float*)d_in[0];
    const void*  ei    = d_in[1];               // dtype detected on device
    const float* Wq    = (const float*)d_in[2];
    const float* bq    = (const float*)d_in[3];
    const float* Wk    = (const float*)d_in[4];
    const float* bk    = (const float*)d_in[5];
    const float* Wv    = (const float*)d_in[6];
    const float* bv    = (const float*)d_in[7];
    const float* Wsk   = (const float*)d_in[8];
    const float* bsk   = (const float*)d_in[9];
    const float* Wl    = (const float*)d_in[10];
    const float* bl    = (const float*)d_in[11];
    const float* Wr    = (const float*)d_in[12];
    const float* br    = (const float*)d_in[13];
    const float* att   = (const float*)d_in[14];
    const float* b_out = (const float*)d_in[15];
    float*       out   = (float*)d_out;

    static float *pQ = nullptr, *pK = nullptr, *pV = nullptr, *pH = nullptr,
                 *pGL = nullptr, *pGR = nullptr, *pXc = nullptr, *pHc = nullptr,
                 *pWqc = nullptr, *pWkc = nullptr, *pWvc = nullptr,
                 *pWsc = nullptr, *pWlc = nullptr, *pWrc = nullptr;
    if (!pQ) {
        void* p;
        cudaGetSymbolAddress(&p, g_Q);   pQ   = (float*)p;
        cudaGetSymbolAddress(&p, g_K);   pK   = (float*)p;
        cudaGetSymbolAddress(&p, g_V);   pV   = (float*)p;
        cudaGetSymbolAddress(&p, g_H);   pH   = (float*)p;
        cudaGetSymbolAddress(&p, g_GL);  pGL  = (float*)p;
        cudaGetSymbolAddress(&p, g_GR);  pGR  = (float*)p;
        cudaGetSymbolAddress(&p, g_Xc);  pXc  = (float*)p;
        cudaGetSymbolAddress(&p, g_Hc);  pHc  = (float*)p;
        cudaGetSymbolAddress(&p, g_Wqc); pWqc = (float*)p;
        cudaGetSymbolAddress(&p, g_Wkc); pWkc = (float*)p;
        cudaGetSymbolAddress(&p, g_Wvc); pWvc = (float*)p;
        cudaGetSymbolAddress(&p, g_Wsc); pWsc = (float*)p;
        cudaGetSymbolAddress(&p, g_Wlc); pWlc = (float*)p;
        cudaGetSymbolAddress(&p, g_Wrc); pWrc = (float*)p;
        cudaFuncSetAttribute(sgemm_tf32,
                             cudaFuncAttributeMaxDynamicSharedMemorySize,
                             SMEM_BYTES);
    }

    const int CV = 256;
    // 5 convert launches, then sgemm at launch index 5 (ncu -s 5 -c 1 window)
    cvt_tf32_kernel<<<(NN * INDIM / 4 + CV - 1) / CV, CV>>>(x,   pXc,  NN * INDIM / 4);
    cvt_tf32_kernel<<<(INDIM * D1N / 4 + CV - 1) / CV, CV>>>(Wq,  pWqc, INDIM * D1N / 4);
    cvt_tf32_kernel<<<(INDIM * D1N / 4 + CV - 1) / CV, CV>>>(Wk,  pWkc, INDIM * D1N / 4);
    cvt_tf32_kernel<<<(INDIM * D1N / 4 + CV - 1) / CV, CV>>>(Wv,  pWvc, INDIM * D1N / 4);
    cvt_tf32_kernel<<<(INDIM * D1N / 4 + CV - 1) / CV, CV>>>(Wsk, pWsc, INDIM * D1N / 4);

    // layer-1 projections: M=10000, K=1024, N=2048
    dim3 g1(D1N / 128, (NN + 127) / 128);
    sgemm_tf32<<<g1, 256, SMEM_BYTES>>>(NN, D1N, INDIM, pXc, pWqc, bq,  pQ);
    sgemm_tf32<<<g1, 256, SMEM_BYTES>>>(NN, D1N, INDIM, pXc, pWkc, bk,  pK);
    sgemm_tf32<<<g1, 256, SMEM_BYTES>>>(NN, D1N, INDIM, pXc, pWvc, bv,  pV);
    sgemm_tf32<<<g1, 256, SMEM_BYTES>>>(NN, D1N, INDIM, pXc, pWsc, bsk, pH);

    // convert layer-2 weights (independent; overlaps nothing but cheap)
    cvt_tf32_kernel<<<((size_t)D1N * D2N / 4 + CV - 1) / CV, CV>>>(Wl, pWlc, D1N * D2N / 4);
    cvt_tf32_kernel<<<((size_t)D1N * D2N / 4 + CV - 1) / CV, CV>>>(Wr, pWrc, D1N * D2N / 4);

    // edge-index dtype detection + unpack; stats + output init
    detect_idx_kernel<<<1, 1>>>((const int*)ei);
    unpack_idx_kernel<<<(EE + 255) / 256, 256>>>(ei);
    init_stats_kernel<<<(NN * H2N + 255) / 256, 256>>>();
    out_init_kernel<<<(NN * C2N + 255) / 256, 256>>>(b_out, out);

    // layer-1 attention + aggregation
    edge_alpha1_kernel<<<EE, H1N * 32>>>();
    exp1_kernel<<<(EE * H1N + 255) / 256, 256>>>();
    agg1_kernel<<<EE, 256>>>();
    elu_cvt_kernel<<<((NN * D1N) / 4 + 255) / 256, 256>>>();

    // layer-2 projections: M=10000, K=2048, N=3680
    dim3 g2((D2N + 127) / 128, (NN + 127) / 128);
    sgemm_tf32<<<g2, 256, SMEM_BYTES>>>(NN, D2N, D1N, pHc, pWlc, bl, pGL);
    sgemm_tf32<<<g2, 256, SMEM_BYTES>>>(NN, D2N, D1N, pHc, pWrc, br, pGR);

    // layer-2 attention + output
    edge_a2_kernel<<<E2N, H2N * 32>>>(att);
    exp2_kernel<<<(E2N * H2N + 255) / 256, 256>>>();
    out_acc_kernel<<<E2N, 256>>>(out);
}